// round 11
// baseline (speedup 1.0000x reference)
#include <cuda_runtime.h>
#include <cstdint>

#define SEQ   2048
#define DIM   64
#define NH    16
#define BM    64
#define BN    64
#define NT    (SEQ / BN)
#define SCALE 0.125f
#define THREADS 128

#define LDK 68      // K/V/Q row stride (floats)
#define LDP 72      // P row stride (conflict-free scalar stores)

typedef unsigned long long ull;

__device__ __forceinline__ ull fma2(ull a, ull b, ull c) {
    ull d; asm("fma.rn.f32x2 %0, %1, %2, %3;" : "=l"(d) : "l"(a), "l"(b), "l"(c)); return d;
}
__device__ __forceinline__ ull dup2(float x) {
    ull d; asm("mov.b64 %0, {%1, %1};" : "=l"(d) : "f"(x)); return d;
}
__device__ __forceinline__ float2 upk(ull a) {
    float2 r; asm("mov.b64 {%0, %1}, %2;" : "=f"(r.x), "=f"(r.y) : "l"(a)); return r;
}
__device__ __forceinline__ uint32_t smem_u32(const void* p) {
    uint32_t a; asm("{ .reg .u64 t; cvta.to.shared.u64 t, %1; cvt.u32.u64 %0, t; }" : "=r"(a) : "l"(p));
    return a;
}
__device__ __forceinline__ void cp16(uint32_t dst, const void* src) {
    asm volatile("cp.async.cg.shared.global [%0], [%1], 16;" :: "r"(dst), "l"(src));
}
#define CP_COMMIT() asm volatile("cp.async.commit_group;" ::: "memory")
#define CP_WAIT(n)  asm volatile("cp.async.wait_group %0;" :: "n"(n) : "memory")

// smem float offsets
#define F_Q    0                          // 64 x LDK
#define F_P    (64 * LDK)                 // 64 x LDP
#define F_K    (F_P + 64 * LDP)           // 2 x (64 x LDK)
#define F_V    (F_K + 2 * 64 * LDK)       // 2 x (64 x LDK)
#define KSZ    (64 * LDK)
#define F_MB   (F_V + 2 * 64 * LDK)       // 64 mask words
#define F_LS   (F_MB + 64)                // 64 rows x 2 partial sums
#define F_MISC (F_LS + 128)
#define SMEM_FLOATS (F_MISC + 4)

extern "C" __global__ void __launch_bounds__(THREADS, 2)
attn_flash7(const float* __restrict__ qg,
            const float* __restrict__ kg,
            const float* __restrict__ vg,
            const unsigned int* __restrict__ maskg,
            float* __restrict__ outg)
{
    extern __shared__ float sm[];
    float* Qs = sm + F_Q;
    float* Ps = sm + F_P;
    unsigned* Mb = (unsigned*)(sm + F_MB);
    float* LS = sm + F_LS;
    int* byteModeP = (int*)(sm + F_MISC);

    const int tid  = threadIdx.x;
    const int wid  = tid >> 5;
    const int lane = tid & 31;
    const int lrow = lane >> 3;
    const int lcol = lane & 7;
    const int wr   = wid >> 1;
    const int wc   = wid & 1;
    const int qrb  = wr * 32 + lrow;
    const int jb   = wc * 32 + lcol;
    const int db   = wc * 32 + 4 * lcol;

    const int bh = blockIdx.y;
    const int qt = blockIdx.x;
    const int batch = bh >> 4;

    const float* Qg = qg + ((size_t)bh * SEQ + (size_t)qt * BM) * DIM;
    const float* Kg = kg + (size_t)bh * SEQ * DIM;
    const float* Vg = vg + (size_t)bh * SEQ * DIM;

    // ---- mask dtype detection ----
    if (tid == 0) *byteModeP = 0;
    __syncthreads();
    { unsigned w = maskg[tid]; if (w > 1u && w != 0x3f800000u) atomicOr(byteModeP, 1); }
    __syncthreads();
    const int byteMode = *byteModeP;

    // ---- mask bitmask ----
    #pragma unroll
    for (int it = 0; it < 16; it++) {
        int i = it * THREADS + tid;
        int e = batch * SEQ + i;
        unsigned keep;
        if (byteMode) keep = (maskg[e >> 2] >> (8 * (e & 3))) & 0xffu;
        else          keep = maskg[e];
        unsigned b = __ballot_sync(0xffffffffu, keep != 0);
        if (lane == 0) Mb[it * 4 + wid] = b;
    }

    // ---- load Q (scale folded) ----
    #pragma unroll
    for (int it = 0; it < 8; it++) {
        int idx = tid + it * THREADS;
        int row = idx >> 4, g = idx & 15;
        float4 t = *reinterpret_cast<const float4*>(Qg + row * DIM + g * 4);
        t.x *= SCALE; t.y *= SCALE; t.z *= SCALE; t.w *= SCALE;
        *reinterpret_cast<float4*>(Qs + row * LDK + 4 * g) = t;
    }

    const uint32_t sb = smem_u32(sm);
    auto cp_k = [&](int kt, int b) {
        uint32_t base = sb + (F_K + b * KSZ) * 4;
        const float* K0 = Kg + (size_t)kt * BN * DIM;
        #pragma unroll
        for (int it = 0; it < 8; it++) {
            int idx = tid + it * THREADS;
            int row = idx >> 4, g = idx & 15;
            cp16(base + (uint32_t)(row * LDK + 4 * g) * 4, K0 + idx * 4);
        }
    };
    auto cp_v = [&](int kt, int b) {
        uint32_t base = sb + (F_V + b * KSZ) * 4;
        const float* V0 = Vg + (size_t)kt * BN * DIM;
        #pragma unroll
        for (int it = 0; it < 8; it++) {
            int idx = tid + it * THREADS;
            int row = idx >> 4, g = idx & 15;
            cp16(base + (uint32_t)(row * LDK + 4 * g) * 4, V0 + idx * 4);
        }
    };

    ull acc[8][4];
    ull o2[8][2];
    float l[8];
    #pragma unroll
    for (int r = 0; r < 8; r++) { o2[r][0] = 0ULL; o2[r][1] = 0ULL; l[r] = 0.f; }

    const float* Qrow = Qs + qrb * LDK;
    float*       PwS  = Ps + qrb * LDP + jb;
    const float* PrS  = Ps + qrb * LDP;

    auto qk_step = [&](int kk, const float* Krow) {
        ulonglong2 q2[8], k2[4];
        #pragma unroll
        for (int c = 0; c < 4; c++)
            k2[c] = *reinterpret_cast<const ulonglong2*>(Krow + c * 8 * LDK + 4 * kk);
        #pragma unroll
        for (int r = 0; r < 8; r++)
            q2[r] = *reinterpret_cast<const ulonglong2*>(Qrow + r * 4 * LDK + 4 * kk);
        #pragma unroll
        for (int r = 0; r < 8; r++)
            #pragma unroll
            for (int c = 0; c < 4; c++) {
                acc[r][c] = fma2(q2[r].x, k2[c].x, acc[r][c]);
                acc[r][c] = fma2(q2[r].y, k2[c].y, acc[r][c]);
            }
    };
    auto pv_step = [&](int j4, const float* Vcol) {
        float4 p4[8];
        #pragma unroll
        for (int r = 0; r < 8; r++)
            p4[r] = *reinterpret_cast<const float4*>(PrS + r * 4 * LDP + 4 * j4);
        #pragma unroll
        for (int jj = 0; jj < 4; jj++) {
            ulonglong2 v2 = *reinterpret_cast<const ulonglong2*>(Vcol + (4 * j4 + jj) * LDK);
            #pragma unroll
            for (int r = 0; r < 8; r++) {
                float pj = (jj == 0) ? p4[r].x : (jj == 1) ? p4[r].y : (jj == 2) ? p4[r].z : p4[r].w;
                ull pd = dup2(pj);
                o2[r][0] = fma2(pd, v2.x, o2[r][0]);
                o2[r][1] = fma2(pd, v2.y, o2[r][1]);
            }
        }
    };
    auto do_exp = [&](int tt) {
        const unsigned wmask = Mb[2 * tt + wc];
        float mv[4];
        #pragma unroll
        for (int c = 0; c < 4; c++)
            mv[c] = ((wmask >> (lcol + 8 * c)) & 1u) ? 0.f : -1e30f;
        #pragma unroll
        for (int r = 0; r < 8; r++) {
            #pragma unroll
            for (int c = 0; c < 4; c++) {
                float2 p = upk(acc[r][c]);
                float e = __expf(p.x + p.y + mv[c]);
                l[r] += e;
                PwS[r * 4 * LDP + 8 * c] = e;
            }
        }
    };
    auto zacc = [&]() {
        #pragma unroll
        for (int r = 0; r < 8; r++)
            #pragma unroll
            for (int c = 0; c < 4; c++) acc[r][c] = 0ULL;
    };

    // ---- prologue: G1{K0,V0}, G2{K1,V1}; QK(0); THEN G3{K2} ----
    cp_k(0, 0); cp_v(0, 0); CP_COMMIT();     // G1
    cp_k(1, 1); cp_v(1, 1); CP_COMMIT();     // G2
    CP_WAIT(1);                  // G1 complete (K0, V0 landed)
    __syncthreads();

    zacc();
    {
        const float* Krow = sm + F_K + jb * LDK;   // buf 0 = K(0)
        #pragma unroll 4
        for (int kk = 0; kk < 16; kk++) qk_step(kk, Krow);
    }
    __syncthreads();             // ALL threads done reading K(0) from buf 0
    cp_k(2, 0); CP_COMMIT();     // G3 — now safe to overwrite K buf 0
    do_exp(0);

    // ---- main loop ----
    for (int t = 0; t < NT - 1; t++) {
        CP_WAIT(1);              // all but newest group done -> {K(t+1), V(t)} landed
        __syncthreads();         // + P(t) visible, + everyone past prior reads

        const float* Krow = sm + F_K + ((t + 1) & 1) * KSZ + jb * LDK;
        const float* Vcol = sm + F_V + (t & 1) * KSZ + db;
        zacc();
        #pragma unroll 2
        for (int i = 0; i < 16; i++) {   // fused: QK(t+1) + PV(t)
            qk_step(i, Krow);
            pv_step(i, Vcol);
        }
        __syncthreads();         // all reads of K(t+1), V(t), P(t) done

        if (t + 3 < NT) cp_k(t + 3, (t + 1) & 1);
        if (t + 2 < NT) cp_v(t + 2, t & 1);
        CP_COMMIT();

        do_exp(t + 1);
    }

    // ---- epilogue: PV(NT-1) ----
    CP_WAIT(0);                  // drain any in-flight groups (e.g. V(NT-1))
    __syncthreads();             // P(NT-1) visible + cp completion across CTA
    {
        const float* Vcol = sm + F_V + ((NT - 1) & 1) * KSZ + db;
        #pragma unroll 2
        for (int i = 0; i < 16; i++) pv_step(i, Vcol);
    }

    // ---- row-sum reduction ----
    #pragma unroll
    for (int r = 0; r < 8; r++) {
        float s = l[r];
        s += __shfl_xor_sync(0xffffffffu, s, 1);
        s += __shfl_xor_sync(0xffffffffu, s, 2);
        s += __shfl_xor_sync(0xffffffffu, s, 4);
        l[r] = s;
    }
    if (lcol == 0) {
        #pragma unroll
        for (int r = 0; r < 8; r++) LS[(qrb + 4 * r) * 2 + wc] = l[r];
    }
    __syncthreads();

    // ---- store ----
    float* Og = outg + ((size_t)bh * SEQ + (size_t)qt * BM) * DIM;
    #pragma unroll
    for (int r = 0; r < 8; r++) {
        int row = qrb + 4 * r;
        float inv = 1.f / (LS[row * 2] + LS[row * 2 + 1]);
        float2 a = upk(o2[r][0]);
        float2 b = upk(o2[r][1]);
        float4 res = make_float4(a.x * inv, a.y * inv, b.x * inv, b.y * inv);
        *reinterpret_cast<float4*>(Og + (size_t)row * DIM + db) = res;
    }
}

extern "C" void kernel_launch(void* const* d_in, const int* in_sizes, int n_in,
                              void* d_out, int out_size)
{
    const float* q = (const float*)d_in[0];
    const float* k = (const float*)d_in[1];
    const float* v = (const float*)d_in[2];
    const unsigned int* mask = (const unsigned int*)d_in[3];
    float* out = (float*)d_out;

    const int smem_bytes = SMEM_FLOATS * (int)sizeof(float);   // ~106.3 KB
    cudaFuncSetAttribute(attn_flash7,
                         cudaFuncAttributeMaxDynamicSharedMemorySize, smem_bytes);

    dim3 grid(NT, 64, 1);
    dim3 block(THREADS, 1, 1);
    attn_flash7<<<grid, block, smem_bytes>>>(q, k, v, mask, out);
}

// round 12
// speedup vs baseline: 1.6858x; 1.6858x over previous
#include <cuda_runtime.h>
#include <cstdint>

#define SEQ   2048
#define DIM   64
#define NH    16
#define BM    64
#define BN    64
#define NT    (SEQ / BN)
#define SCALE 0.125f
#define THREADS 128

#define LDK 68      // K/V/Q row stride (floats)
#define LDP 72      // P row stride (conflict-free scalar stores)

typedef unsigned long long ull;

__device__ __forceinline__ ull fma2(ull a, ull b, ull c) {
    ull d; asm("fma.rn.f32x2 %0, %1, %2, %3;" : "=l"(d) : "l"(a), "l"(b), "l"(c)); return d;
}
__device__ __forceinline__ ull dup2(float x) {
    ull d; asm("mov.b64 %0, {%1, %1};" : "=l"(d) : "f"(x)); return d;
}
__device__ __forceinline__ float2 upk(ull a) {
    float2 r; asm("mov.b64 {%0, %1}, %2;" : "=f"(r.x), "=f"(r.y) : "l"(a)); return r;
}
__device__ __forceinline__ uint32_t smem_u32(const void* p) {
    uint32_t a; asm("{ .reg .u64 t; cvta.to.shared.u64 t, %1; cvt.u32.u64 %0, t; }" : "=r"(a) : "l"(p));
    return a;
}
__device__ __forceinline__ void cp16(uint32_t dst, const void* src) {
    asm volatile("cp.async.cg.shared.global [%0], [%1], 16;" :: "r"(dst), "l"(src));
}
#define CP_COMMIT() asm volatile("cp.async.commit_group;" ::: "memory")
#define CP_WAIT(n)  asm volatile("cp.async.wait_group %0;" :: "n"(n) : "memory")

// smem float offsets
#define F_Q    0                          // 64 x LDK
#define F_P    (64 * LDK)                 // 64 x LDP
#define F_K    (F_P + 64 * LDP)           // 2 x (64 x LDK)
#define F_V    (F_K + 2 * 64 * LDK)       // 2 x (64 x LDK)
#define KSZ    (64 * LDK)
#define F_MB   (F_V + 2 * 64 * LDK)       // 64 mask words
#define F_LS   (F_MB + 64)                // 64 rows x 2 partial sums
#define F_MISC (F_LS + 128)
#define SMEM_FLOATS (F_MISC + 4)

extern "C" __global__ void __launch_bounds__(THREADS, 2)
attn_flash8(const float* __restrict__ qg,
            const float* __restrict__ kg,
            const float* __restrict__ vg,
            const unsigned int* __restrict__ maskg,
            float* __restrict__ outg)
{
    extern __shared__ float sm[];
    float* Qs = sm + F_Q;
    float* Ps = sm + F_P;
    unsigned* Mb = (unsigned*)(sm + F_MB);
    float* LS = sm + F_LS;
    int* byteModeP = (int*)(sm + F_MISC);

    const int tid  = threadIdx.x;
    const int wid  = tid >> 5;
    const int lane = tid & 31;
    const int lrow = lane >> 3;
    const int lcol = lane & 7;
    const int wr   = wid >> 1;
    const int wc   = wid & 1;
    const int qrb  = wr * 32 + lrow;
    const int jb   = wc * 32 + lcol;
    const int db   = wc * 32 + 4 * lcol;

    const int bh = blockIdx.y;
    const int qt = blockIdx.x;
    const int batch = bh >> 4;

    const float* Qg = qg + ((size_t)bh * SEQ + (size_t)qt * BM) * DIM;
    const float* Kg = kg + (size_t)bh * SEQ * DIM;
    const float* Vg = vg + (size_t)bh * SEQ * DIM;

    // ---- mask dtype detection ----
    if (tid == 0) *byteModeP = 0;
    __syncthreads();
    { unsigned w = maskg[tid]; if (w > 1u && w != 0x3f800000u) atomicOr(byteModeP, 1); }
    __syncthreads();
    const int byteMode = *byteModeP;

    // ---- mask bitmask ----
    #pragma unroll
    for (int it = 0; it < 16; it++) {
        int i = it * THREADS + tid;
        int e = batch * SEQ + i;
        unsigned keep;
        if (byteMode) keep = (maskg[e >> 2] >> (8 * (e & 3))) & 0xffu;
        else          keep = maskg[e];
        unsigned b = __ballot_sync(0xffffffffu, keep != 0);
        if (lane == 0) Mb[it * 4 + wid] = b;
    }

    // ---- load Q (scale folded) ----
    #pragma unroll
    for (int it = 0; it < 8; it++) {
        int idx = tid + it * THREADS;
        int row = idx >> 4, g = idx & 15;
        float4 t = *reinterpret_cast<const float4*>(Qg + row * DIM + g * 4);
        t.x *= SCALE; t.y *= SCALE; t.z *= SCALE; t.w *= SCALE;
        *reinterpret_cast<float4*>(Qs + row * LDK + 4 * g) = t;
    }

    const uint32_t sb = smem_u32(sm);
    auto cp_k = [&](int kt, int b) {
        uint32_t base = sb + (F_K + b * KSZ) * 4;
        const float* K0 = Kg + (size_t)kt * BN * DIM;
        #pragma unroll
        for (int it = 0; it < 8; it++) {
            int idx = tid + it * THREADS;
            int row = idx >> 4, g = idx & 15;
            cp16(base + (uint32_t)(row * LDK + 4 * g) * 4, K0 + idx * 4);
        }
    };
    auto cp_v = [&](int kt, int b) {
        uint32_t base = sb + (F_V + b * KSZ) * 4;
        const float* V0 = Vg + (size_t)kt * BN * DIM;
        #pragma unroll
        for (int it = 0; it < 8; it++) {
            int idx = tid + it * THREADS;
            int row = idx >> 4, g = idx & 15;
            cp16(base + (uint32_t)(row * LDK + 4 * g) * 4, V0 + idx * 4);
        }
    };

    ull acc[8][4];
    ull o2[8][2];
    float l[8];
    #pragma unroll
    for (int r = 0; r < 8; r++) { o2[r][0] = 0ULL; o2[r][1] = 0ULL; l[r] = 0.f; }

    const float* Qrow = Qs + qrb * LDK;
    float*       PwS  = Ps + qrb * LDP + jb;
    const float* PrS  = Ps + qrb * LDP;

    // low-pressure QK step: stage only k2[4]; q2 transient per row
    auto qk_step = [&](int kk, const float* Krow) {
        ulonglong2 k2[4];
        #pragma unroll
        for (int c = 0; c < 4; c++)
            k2[c] = *reinterpret_cast<const ulonglong2*>(Krow + c * 8 * LDK + 4 * kk);
        #pragma unroll
        for (int r = 0; r < 8; r++) {
            ulonglong2 q2 = *reinterpret_cast<const ulonglong2*>(Qrow + r * 4 * LDK + 4 * kk);
            #pragma unroll
            for (int c = 0; c < 4; c++) {
                acc[r][c] = fma2(q2.x, k2[c].x, acc[r][c]);
                acc[r][c] = fma2(q2.y, k2[c].y, acc[r][c]);
            }
        }
    };
    // low-pressure PV step: stage only v2[4]; p4 transient per row
    auto pv_step = [&](int j4, const float* Vcol) {
        ulonglong2 v2[4];
        #pragma unroll
        for (int jj = 0; jj < 4; jj++)
            v2[jj] = *reinterpret_cast<const ulonglong2*>(Vcol + (4 * j4 + jj) * LDK);
        #pragma unroll
        for (int r = 0; r < 8; r++) {
            float4 p4 = *reinterpret_cast<const float4*>(PrS + r * 4 * LDP + 4 * j4);
            ull pd0 = dup2(p4.x), pd1 = dup2(p4.y), pd2 = dup2(p4.z), pd3 = dup2(p4.w);
            o2[r][0] = fma2(pd0, v2[0].x, o2[r][0]); o2[r][1] = fma2(pd0, v2[0].y, o2[r][1]);
            o2[r][0] = fma2(pd1, v2[1].x, o2[r][0]); o2[r][1] = fma2(pd1, v2[1].y, o2[r][1]);
            o2[r][0] = fma2(pd2, v2[2].x, o2[r][0]); o2[r][1] = fma2(pd2, v2[2].y, o2[r][1]);
            o2[r][0] = fma2(pd3, v2[3].x, o2[r][0]); o2[r][1] = fma2(pd3, v2[3].y, o2[r][1]);
        }
    };
    auto do_exp = [&](int tt) {
        const unsigned wmask = Mb[2 * tt + wc];
        float mv[4];
        #pragma unroll
        for (int c = 0; c < 4; c++)
            mv[c] = ((wmask >> (lcol + 8 * c)) & 1u) ? 0.f : -1e30f;
        #pragma unroll
        for (int r = 0; r < 8; r++) {
            #pragma unroll
            for (int c = 0; c < 4; c++) {
                float2 p = upk(acc[r][c]);
                float e = __expf(p.x + p.y + mv[c]);
                l[r] += e;
                PwS[r * 4 * LDP + 8 * c] = e;
            }
        }
    };
    auto zacc = [&]() {
        #pragma unroll
        for (int r = 0; r < 8; r++)
            #pragma unroll
            for (int c = 0; c < 4; c++) acc[r][c] = 0ULL;
    };

    // ---- prologue: G1{K0,V0}, G2{K1,V1}; QK(0); THEN G3{K2} ----
    cp_k(0, 0); cp_v(0, 0); CP_COMMIT();     // G1
    cp_k(1, 1); cp_v(1, 1); CP_COMMIT();     // G2
    CP_WAIT(1);                  // G1 complete (K0, V0 landed)
    __syncthreads();

    zacc();
    {
        const float* Krow = sm + F_K + jb * LDK;   // buf 0 = K(0)
        #pragma unroll 4
        for (int kk = 0; kk < 16; kk++) qk_step(kk, Krow);
    }
    __syncthreads();             // ALL threads done reading K(0) from buf 0
    cp_k(2, 0); CP_COMMIT();     // G3 — safe to overwrite K buf 0
    do_exp(0);

    // ---- main loop ----
    for (int t = 0; t < NT - 1; t++) {
        CP_WAIT(1);              // {K(t+1), V(t)} landed
        __syncthreads();         // + P(t) visible

        const float* Krow = sm + F_K + ((t + 1) & 1) * KSZ + jb * LDK;
        const float* Vcol = sm + F_V + (t & 1) * KSZ + db;
        zacc();
        #pragma unroll 4
        for (int i = 0; i < 16; i++) {   // fused: QK(t+1) + PV(t)
            qk_step(i, Krow);
            pv_step(i, Vcol);
        }
        __syncthreads();         // all reads of K(t+1), V(t), P(t) done

        if (t + 3 < NT) cp_k(t + 3, (t + 1) & 1);
        if (t + 2 < NT) cp_v(t + 2, t & 1);
        CP_COMMIT();

        do_exp(t + 1);
    }

    // ---- epilogue: PV(NT-1) ----
    CP_WAIT(0);
    __syncthreads();             // P(NT-1) visible
    {
        const float* Vcol = sm + F_V + ((NT - 1) & 1) * KSZ + db;
        #pragma unroll 4
        for (int i = 0; i < 16; i++) pv_step(i, Vcol);
    }

    // ---- row-sum reduction ----
    #pragma unroll
    for (int r = 0; r < 8; r++) {
        float s = l[r];
        s += __shfl_xor_sync(0xffffffffu, s, 1);
        s += __shfl_xor_sync(0xffffffffu, s, 2);
        s += __shfl_xor_sync(0xffffffffu, s, 4);
        l[r] = s;
    }
    if (lcol == 0) {
        #pragma unroll
        for (int r = 0; r < 8; r++) LS[(qrb + 4 * r) * 2 + wc] = l[r];
    }
    __syncthreads();

    // ---- store ----
    float* Og = outg + ((size_t)bh * SEQ + (size_t)qt * BM) * DIM;
    #pragma unroll
    for (int r = 0; r < 8; r++) {
        int row = qrb + 4 * r;
        float inv = 1.f / (LS[row * 2] + LS[row * 2 + 1]);
        float2 a = upk(o2[r][0]);
        float2 b = upk(o2[r][1]);
        float4 res = make_float4(a.x * inv, a.y * inv, b.x * inv, b.y * inv);
        *reinterpret_cast<float4*>(Og + (size_t)row * DIM + db) = res;
    }
}

extern "C" void kernel_launch(void* const* d_in, const int* in_sizes, int n_in,
                              void* d_out, int out_size)
{
    const float* q = (const float*)d_in[0];
    const float* k = (const float*)d_in[1];
    const float* v = (const float*)d_in[2];
    const unsigned int* mask = (const unsigned int*)d_in[3];
    float* out = (float*)d_out;

    const int smem_bytes = SMEM_FLOATS * (int)sizeof(float);   // ~106.3 KB
    cudaFuncSetAttribute(attn_flash8,
                         cudaFuncAttributeMaxDynamicSharedMemorySize, smem_bytes);

    dim3 grid(NT, 64, 1);
    dim3 block(THREADS, 1, 1);
    attn_flash8<<<grid, block, smem_bytes>>>(q, k, v, mask, out);
}

// round 13
// speedup vs baseline: 1.7055x; 1.0117x over previous
#include <cuda_runtime.h>
#include <cstdint>

#define SEQ   2048
#define DIM   64
#define NH    16
#define BM    64
#define BN    64
#define NT    (SEQ / BN)
#define SCALE 0.125f
#define THREADS 128

#define LDK 68
#define LDP 72

typedef unsigned long long ull;

__device__ __forceinline__ ull fma2(ull a, ull b, ull c) {
    ull d; asm("fma.rn.f32x2 %0, %1, %2, %3;" : "=l"(d) : "l"(a), "l"(b), "l"(c)); return d;
}
__device__ __forceinline__ ull dup2(float x) {
    ull d; asm("mov.b64 %0, {%1, %1};" : "=l"(d) : "f"(x)); return d;
}
__device__ __forceinline__ float2 upk(ull a) {
    float2 r; asm("mov.b64 {%0, %1}, %2;" : "=f"(r.x), "=f"(r.y) : "l"(a)); return r;
}
__device__ __forceinline__ uint32_t smem_u32(const void* p) {
    uint32_t a; asm("{ .reg .u64 t; cvta.to.shared.u64 t, %1; cvt.u32.u64 %0, t; }" : "=r"(a) : "l"(p));
    return a;
}
__device__ __forceinline__ void cp16(uint32_t dst, const void* src) {
    asm volatile("cp.async.cg.shared.global [%0], [%1], 16;" :: "r"(dst), "l"(src));
}
#define CP_COMMIT() asm volatile("cp.async.commit_group;" ::: "memory")
#define CP_WAIT(n)  asm volatile("cp.async.wait_group %0;" :: "n"(n) : "memory")

// smem float offsets
#define F_Q    0
#define F_P    (64 * LDK)
#define F_K    (F_P + 64 * LDP)
#define F_V    (F_K + 2 * 64 * LDK)
#define KSZ    (64 * LDK)
#define F_MB   (F_V + 2 * 64 * LDK)
#define F_LS   (F_MB + 64)
#define F_MISC (F_LS + 128)
#define SMEM_FLOATS (F_MISC + 4)

extern "C" __global__ void __launch_bounds__(THREADS, 2)
attn_flash9(const float* __restrict__ qg,
            const float* __restrict__ kg,
            const float* __restrict__ vg,
            const unsigned int* __restrict__ maskg,
            float* __restrict__ outg)
{
    extern __shared__ float sm[];
    float* Qs = sm + F_Q;
    float* Ps = sm + F_P;
    unsigned* Mb = (unsigned*)(sm + F_MB);
    float* LS = sm + F_LS;
    int* byteModeP = (int*)(sm + F_MISC);

    const int tid  = threadIdx.x;
    const int wid  = tid >> 5;
    const int lane = tid & 31;
    const int lrow = lane >> 3;
    const int lcol = lane & 7;
    const int wr   = wid >> 1;
    const int wc   = wid & 1;
    const int qrb  = wr * 32 + lrow;       // + 4*r -> rows
    const int jb   = wc * 32 + lcol;       // + 8*c -> S cols (warp j band = wc*32..+31)

    const int bh = blockIdx.y;
    const int qt = blockIdx.x;
    const int batch = bh >> 4;

    const float* Qg = qg + ((size_t)bh * SEQ + (size_t)qt * BM) * DIM;
    const float* Kg = kg + (size_t)bh * SEQ * DIM;
    const float* Vg = vg + (size_t)bh * SEQ * DIM;

    // ---- mask dtype detection ----
    if (tid == 0) *byteModeP = 0;
    __syncthreads();
    { unsigned w = maskg[tid]; if (w > 1u && w != 0x3f800000u) atomicOr(byteModeP, 1); }
    __syncthreads();
    const int byteMode = *byteModeP;

    // ---- mask bitmask ----
    #pragma unroll
    for (int it = 0; it < 16; it++) {
        int i = it * THREADS + tid;
        int e = batch * SEQ + i;
        unsigned keep;
        if (byteMode) keep = (maskg[e >> 2] >> (8 * (e & 3))) & 0xffu;
        else          keep = maskg[e];
        unsigned b = __ballot_sync(0xffffffffu, keep != 0);
        if (lane == 0) Mb[it * 4 + wid] = b;
    }

    // ---- load Q (scale folded) ----
    #pragma unroll
    for (int it = 0; it < 8; it++) {
        int idx = tid + it * THREADS;
        int row = idx >> 4, g = idx & 15;
        float4 t = *reinterpret_cast<const float4*>(Qg + row * DIM + g * 4);
        t.x *= SCALE; t.y *= SCALE; t.z *= SCALE; t.w *= SCALE;
        *reinterpret_cast<float4*>(Qs + row * LDK + 4 * g) = t;
    }

    const uint32_t sb = smem_u32(sm);
    auto cp_k = [&](int kt, int b) {
        uint32_t base = sb + (F_K + b * KSZ) * 4;
        const float* K0 = Kg + (size_t)kt * BN * DIM;
        #pragma unroll
        for (int it = 0; it < 8; it++) {
            int idx = tid + it * THREADS;
            int row = idx >> 4, g = idx & 15;
            cp16(base + (uint32_t)(row * LDK + 4 * g) * 4, K0 + idx * 4);
        }
    };
    auto cp_v = [&](int kt, int b) {
        uint32_t base = sb + (F_V + b * KSZ) * 4;
        const float* V0 = Vg + (size_t)kt * BN * DIM;
        #pragma unroll
        for (int it = 0; it < 8; it++) {
            int idx = tid + it * THREADS;
            int row = idx >> 4, g = idx & 15;
            cp16(base + (uint32_t)(row * LDK + 4 * g) * 4, V0 + idx * 4);
        }
    };

    ull acc[8][4];
    ull o2[8][4];       // [r][quad0.lo, quad0.hi, quad1.lo, quad1.hi]  d = 4*lcol and 32+4*lcol
    float l[8];
    #pragma unroll
    for (int r = 0; r < 8; r++) {
        o2[r][0] = 0ULL; o2[r][1] = 0ULL; o2[r][2] = 0ULL; o2[r][3] = 0ULL; l[r] = 0.f;
    }

    const float* Qrow = Qs + qrb * LDK;
    float*       PwS  = Ps + qrb * LDP + jb;
    const float* PrS  = Ps + qrb * LDP;

    auto qk_step = [&](int kk, const float* Krow) {
        ulonglong2 k2[4];
        #pragma unroll
        for (int c = 0; c < 4; c++)
            k2[c] = *reinterpret_cast<const ulonglong2*>(Krow + c * 8 * LDK + 4 * kk);
        #pragma unroll
        for (int r = 0; r < 8; r++) {
            ulonglong2 q2 = *reinterpret_cast<const ulonglong2*>(Qrow + r * 4 * LDK + 4 * kk);
            #pragma unroll
            for (int c = 0; c < 4; c++) {
                acc[r][c] = fma2(q2.x, k2[c].x, acc[r][c]);
                acc[r][c] = fma2(q2.y, k2[c].y, acc[r][c]);
            }
        }
    };
    // PV over warp's own 32 js (4 per call), all 64 d (two quads per thread)
    auto pv_step = [&](int j4, const float* Vs) {
        const float* Vbase = Vs + (wc * 32 + 4 * j4) * LDK + 4 * lcol;
        ulonglong2 va[4], vb[4];
        #pragma unroll
        for (int jj = 0; jj < 4; jj++) {
            va[jj] = *reinterpret_cast<const ulonglong2*>(Vbase + jj * LDK);
            vb[jj] = *reinterpret_cast<const ulonglong2*>(Vbase + jj * LDK + 32);
        }
        #pragma unroll
        for (int r = 0; r < 8; r++) {
            float4 p4 = *reinterpret_cast<const float4*>(PrS + r * 4 * LDP + wc * 32 + 4 * j4);
            ull pd;
            pd = dup2(p4.x);
            o2[r][0] = fma2(pd, va[0].x, o2[r][0]); o2[r][1] = fma2(pd, va[0].y, o2[r][1]);
            o2[r][2] = fma2(pd, vb[0].x, o2[r][2]); o2[r][3] = fma2(pd, vb[0].y, o2[r][3]);
            pd = dup2(p4.y);
            o2[r][0] = fma2(pd, va[1].x, o2[r][0]); o2[r][1] = fma2(pd, va[1].y, o2[r][1]);
            o2[r][2] = fma2(pd, vb[1].x, o2[r][2]); o2[r][3] = fma2(pd, vb[1].y, o2[r][3]);
            pd = dup2(p4.z);
            o2[r][0] = fma2(pd, va[2].x, o2[r][0]); o2[r][1] = fma2(pd, va[2].y, o2[r][1]);
            o2[r][2] = fma2(pd, vb[2].x, o2[r][2]); o2[r][3] = fma2(pd, vb[2].y, o2[r][3]);
            pd = dup2(p4.w);
            o2[r][0] = fma2(pd, va[3].x, o2[r][0]); o2[r][1] = fma2(pd, va[3].y, o2[r][1]);
            o2[r][2] = fma2(pd, vb[3].x, o2[r][2]); o2[r][3] = fma2(pd, vb[3].y, o2[r][3]);
        }
    };
    auto do_exp = [&](int tt) {
        const unsigned wmask = Mb[2 * tt + wc];
        float mv[4];
        #pragma unroll
        for (int c = 0; c < 4; c++)
            mv[c] = ((wmask >> (lcol + 8 * c)) & 1u) ? 0.f : -1e30f;
        #pragma unroll
        for (int r = 0; r < 8; r++) {
            #pragma unroll
            for (int c = 0; c < 4; c++) {
                float2 p = upk(acc[r][c]);
                float e = __expf(p.x + p.y + mv[c]);
                l[r] += e;
                PwS[r * 4 * LDP + 8 * c] = e;
            }
        }
        __syncwarp();            // P is warp-private: producer == consumer warp
    };
    auto zacc = [&]() {
        #pragma unroll
        for (int r = 0; r < 8; r++)
            #pragma unroll
            for (int c = 0; c < 4; c++) acc[r][c] = 0ULL;
    };

    // ---- prologue: G1{K0,V0}, G2{K1,V1}; QK(0); then G3{K2} ----
    cp_k(0, 0); cp_v(0, 0); CP_COMMIT();
    cp_k(1, 1); cp_v(1, 1); CP_COMMIT();
    CP_WAIT(1);
    __syncthreads();

    zacc();
    {
        const float* Krow = sm + F_K + jb * LDK;
        #pragma unroll 4
        for (int kk = 0; kk < 16; kk++) qk_step(kk, Krow);
    }
    __syncthreads();             // all reads of K(0) buf0 done
    cp_k(2, 0); CP_COMMIT();
    do_exp(0);

    // ---- main loop ----
    for (int t = 0; t < NT - 1; t++) {
        CP_WAIT(1);              // {K(t+1), V(t)} landed
        __syncthreads();

        const float* Krow = sm + F_K + ((t + 1) & 1) * KSZ + jb * LDK;
        const float* Vs   = sm + F_V + (t & 1) * KSZ;
        zacc();
        #pragma unroll 4
        for (int i = 0; i < 16; i++) {   // fused: QK(t+1) 16 steps + PV(t) 8 steps
            qk_step(i, Krow);
            if ((i & 1) == 0) pv_step(i >> 1, Vs);
        }
        __syncthreads();         // reads of K(t+1), V(t) done

        if (t + 3 < NT) cp_k(t + 3, (t + 1) & 1);
        if (t + 2 < NT) cp_v(t + 2, t & 1);
        CP_COMMIT();

        do_exp(t + 1);
    }

    // ---- epilogue: PV(NT-1) ----
    CP_WAIT(0);
    __syncthreads();             // V(NT-1) visible CTA-wide
    {
        const float* Vs = sm + F_V + ((NT - 1) & 1) * KSZ;
        #pragma unroll 4
        for (int i = 0; i < 8; i++) pv_step(i, Vs);
    }

    // ---- row-sum reduction (8 lcol lanes, then 2 wc warps via LS) ----
    #pragma unroll
    for (int r = 0; r < 8; r++) {
        float s = l[r];
        s += __shfl_xor_sync(0xffffffffu, s, 1);
        s += __shfl_xor_sync(0xffffffffu, s, 2);
        s += __shfl_xor_sync(0xffffffffu, s, 4);
        l[r] = s;
    }
    if (lcol == 0) {
        #pragma unroll
        for (int r = 0; r < 8; r++) LS[(qrb + 4 * r) * 2 + wc] = l[r];
    }

    // ---- cross-warp O reduce: wc=1 dumps partials into Ps ----
    __syncthreads();             // all PV reads of Ps done; LS populated
    if (wc == 1) {
        #pragma unroll
        for (int r = 0; r < 8; r++) {
            int row = qrb + 4 * r;
            float2 a0 = upk(o2[r][0]), a1 = upk(o2[r][1]);
            float2 b0 = upk(o2[r][2]), b1 = upk(o2[r][3]);
            *reinterpret_cast<float4*>(Ps + row * LDP + 4 * lcol)      = make_float4(a0.x, a0.y, a1.x, a1.y);
            *reinterpret_cast<float4*>(Ps + row * LDP + 32 + 4 * lcol) = make_float4(b0.x, b0.y, b1.x, b1.y);
        }
    }
    __syncthreads();

    if (wc == 0) {
        float* Og = outg + ((size_t)bh * SEQ + (size_t)qt * BM) * DIM;
        #pragma unroll
        for (int r = 0; r < 8; r++) {
            int row = qrb + 4 * r;
            float inv = 1.f / (LS[row * 2] + LS[row * 2 + 1]);
            float4 q0 = *reinterpret_cast<const float4*>(Ps + row * LDP + 4 * lcol);
            float4 q1 = *reinterpret_cast<const float4*>(Ps + row * LDP + 32 + 4 * lcol);
            float2 a0 = upk(o2[r][0]), a1 = upk(o2[r][1]);
            float2 b0 = upk(o2[r][2]), b1 = upk(o2[r][3]);
            *reinterpret_cast<float4*>(Og + (size_t)row * DIM + 4 * lcol) =
                make_float4((a0.x + q0.x) * inv, (a0.y + q0.y) * inv,
                            (a1.x + q0.z) * inv, (a1.y + q0.w) * inv);
            *reinterpret_cast<float4*>(Og + (size_t)row * DIM + 32 + 4 * lcol) =
                make_float4((b0.x + q1.x) * inv, (b0.y + q1.y) * inv,
                            (b1.x + q1.z) * inv, (b1.y + q1.w) * inv);
        }
    }
}

extern "C" void kernel_launch(void* const* d_in, const int* in_sizes, int n_in,
                              void* d_out, int out_size)
{
    const float* q = (const float*)d_in[0];
    const float* k = (const float*)d_in[1];
    const float* v = (const float*)d_in[2];
    const unsigned int* mask = (const unsigned int*)d_in[3];
    float* out = (float*)d_out;

    const int smem_bytes = SMEM_FLOATS * (int)sizeof(float);
    cudaFuncSetAttribute(attn_flash9,
                         cudaFuncAttributeMaxDynamicSharedMemorySize, smem_bytes);

    dim3 grid(NT, 64, 1);
    dim3 block(THREADS, 1, 1);
    attn_flash9<<<grid, block, smem_bytes>>>(q, k, v, mask, out);
}

// round 14
// speedup vs baseline: 1.7593x; 1.0316x over previous
#include <cuda_runtime.h>
#include <cstdint>

#define SEQ   2048
#define DIM   64
#define NH    16
#define BM    64
#define BN    64
#define NT    (SEQ / BN)
#define SCALE2 0.1803368801111204f   // 0.125 * log2(e): exp(s)=exp2(s')
#define THREADS 128

#define LDK 68
#define LDP 72

typedef unsigned long long ull;

__device__ __forceinline__ ull fma2(ull a, ull b, ull c) {
    ull d; asm("fma.rn.f32x2 %0, %1, %2, %3;" : "=l"(d) : "l"(a), "l"(b), "l"(c)); return d;
}
__device__ __forceinline__ ull dup2(float x) {
    ull d; asm("mov.b64 %0, {%1, %1};" : "=l"(d) : "f"(x)); return d;
}
__device__ __forceinline__ float2 upk(ull a) {
    float2 r; asm("mov.b64 {%0, %1}, %2;" : "=f"(r.x), "=f"(r.y) : "l"(a)); return r;
}
__device__ __forceinline__ float ex2(float x) {
    float r; asm("ex2.approx.ftz.f32 %0, %1;" : "=f"(r) : "f"(x)); return r;
}
__device__ __forceinline__ uint32_t smem_u32(const void* p) {
    uint32_t a; asm("{ .reg .u64 t; cvta.to.shared.u64 t, %1; cvt.u32.u64 %0, t; }" : "=r"(a) : "l"(p));
    return a;
}
__device__ __forceinline__ void cp16(uint32_t dst, const void* src) {
    asm volatile("cp.async.cg.shared.global [%0], [%1], 16;" :: "r"(dst), "l"(src));
}
#define CP_COMMIT() asm volatile("cp.async.commit_group;" ::: "memory")
#define CP_WAIT(n)  asm volatile("cp.async.wait_group %0;" :: "n"(n) : "memory")

// smem float offsets
#define F_Q    0
#define F_P    (64 * LDK)
#define F_K    (F_P + 64 * LDP)
#define F_V    (F_K + 2 * 64 * LDK)
#define KSZ    (64 * LDK)
#define F_MB   (F_V + 2 * 64 * LDK)
#define F_LS   (F_MB + 64)
#define F_MISC (F_LS + 128)
#define SMEM_FLOATS (F_MISC + 4)

extern "C" __global__ void __launch_bounds__(THREADS, 2)
attn_flash10(const float* __restrict__ qg,
             const float* __restrict__ kg,
             const float* __restrict__ vg,
             const unsigned int* __restrict__ maskg,
             float* __restrict__ outg)
{
    extern __shared__ float sm[];
    float* Qs = sm + F_Q;
    float* Ps = sm + F_P;
    unsigned* Mb = (unsigned*)(sm + F_MB);
    float* LS = sm + F_LS;
    int* byteModeP = (int*)(sm + F_MISC);

    const int tid  = threadIdx.x;
    const int wid  = tid >> 5;
    const int lane = tid & 31;
    const int lrow = lane >> 3;
    const int lcol = lane & 7;
    const int wr   = wid >> 1;
    const int wc   = wid & 1;
    const int qrb  = wr * 32 + lrow;
    const int jb   = wc * 32 + lcol;

    const int bh = blockIdx.y;
    const int qt = blockIdx.x;
    const int batch = bh >> 4;

    const float* Qg = qg + ((size_t)bh * SEQ + (size_t)qt * BM) * DIM;
    const float* Kg = kg + (size_t)bh * SEQ * DIM;
    const float* Vg = vg + (size_t)bh * SEQ * DIM;

    // ---- mask dtype detection ----
    if (tid == 0) *byteModeP = 0;
    __syncthreads();
    { unsigned w = maskg[tid]; if (w > 1u && w != 0x3f800000u) atomicOr(byteModeP, 1); }
    __syncthreads();
    const int byteMode = *byteModeP;

    // ---- mask bitmask ----
    #pragma unroll
    for (int it = 0; it < 16; it++) {
        int i = it * THREADS + tid;
        int e = batch * SEQ + i;
        unsigned keep;
        if (byteMode) keep = (maskg[e >> 2] >> (8 * (e & 3))) & 0xffu;
        else          keep = maskg[e];
        unsigned b = __ballot_sync(0xffffffffu, keep != 0);
        if (lane == 0) Mb[it * 4 + wid] = b;
    }

    // ---- load Q (scale*log2e folded) ----
    #pragma unroll
    for (int it = 0; it < 8; it++) {
        int idx = tid + it * THREADS;
        int row = idx >> 4, g = idx & 15;
        float4 t = *reinterpret_cast<const float4*>(Qg + row * DIM + g * 4);
        t.x *= SCALE2; t.y *= SCALE2; t.z *= SCALE2; t.w *= SCALE2;
        *reinterpret_cast<float4*>(Qs + row * LDK + 4 * g) = t;
    }

    const uint32_t sb = smem_u32(sm);
    auto cp_k = [&](int kt, int b) {
        uint32_t base = sb + (F_K + b * KSZ) * 4;
        const float* K0 = Kg + (size_t)kt * BN * DIM;
        #pragma unroll
        for (int it = 0; it < 8; it++) {
            int idx = tid + it * THREADS;
            int row = idx >> 4, g = idx & 15;
            cp16(base + (uint32_t)(row * LDK + 4 * g) * 4, K0 + idx * 4);
        }
    };
    auto cp_v = [&](int kt, int b) {
        uint32_t base = sb + (F_V + b * KSZ) * 4;
        const float* V0 = Vg + (size_t)kt * BN * DIM;
        #pragma unroll
        for (int it = 0; it < 8; it++) {
            int idx = tid + it * THREADS;
            int row = idx >> 4, g = idx & 15;
            cp16(base + (uint32_t)(row * LDK + 4 * g) * 4, V0 + idx * 4);
        }
    };

    ull acc[8][4];
    ull o2[8][4];
    float l[8];
    #pragma unroll
    for (int r = 0; r < 8; r++) {
        o2[r][0] = 0ULL; o2[r][1] = 0ULL; o2[r][2] = 0ULL; o2[r][3] = 0ULL; l[r] = 0.f;
    }

    const float* Qrow = Qs + qrb * LDK;
    float*       PwS  = Ps + qrb * LDP + jb;
    const float* PrS  = Ps + qrb * LDP;

    auto qk_step = [&](int kk, const float* Krow) {
        ulonglong2 k2[4];
        #pragma unroll
        for (int c = 0; c < 4; c++)
            k2[c] = *reinterpret_cast<const ulonglong2*>(Krow + c * 8 * LDK + 4 * kk);
        #pragma unroll
        for (int r = 0; r < 8; r++) {
            ulonglong2 q2 = *reinterpret_cast<const ulonglong2*>(Qrow + r * 4 * LDK + 4 * kk);
            #pragma unroll
            for (int c = 0; c < 4; c++) {
                acc[r][c] = fma2(q2.x, k2[c].x, acc[r][c]);
                acc[r][c] = fma2(q2.y, k2[c].y, acc[r][c]);
            }
        }
    };
    auto pv_step = [&](int j4, const float* Vs) {
        const float* Vbase = Vs + (wc * 32 + 4 * j4) * LDK + 4 * lcol;
        ulonglong2 va[4], vb[4];
        #pragma unroll
        for (int jj = 0; jj < 4; jj++) {
            va[jj] = *reinterpret_cast<const ulonglong2*>(Vbase + jj * LDK);
            vb[jj] = *reinterpret_cast<const ulonglong2*>(Vbase + jj * LDK + 32);
        }
        #pragma unroll
        for (int r = 0; r < 8; r++) {
            float4 p4 = *reinterpret_cast<const float4*>(PrS + r * 4 * LDP + wc * 32 + 4 * j4);
            ull pd;
            pd = dup2(p4.x);
            o2[r][0] = fma2(pd, va[0].x, o2[r][0]); o2[r][1] = fma2(pd, va[0].y, o2[r][1]);
            o2[r][2] = fma2(pd, vb[0].x, o2[r][2]); o2[r][3] = fma2(pd, vb[0].y, o2[r][3]);
            pd = dup2(p4.y);
            o2[r][0] = fma2(pd, va[1].x, o2[r][0]); o2[r][1] = fma2(pd, va[1].y, o2[r][1]);
            o2[r][2] = fma2(pd, vb[1].x, o2[r][2]); o2[r][3] = fma2(pd, vb[1].y, o2[r][3]);
            pd = dup2(p4.z);
            o2[r][0] = fma2(pd, va[2].x, o2[r][0]); o2[r][1] = fma2(pd, va[2].y, o2[r][1]);
            o2[r][2] = fma2(pd, vb[2].x, o2[r][2]); o2[r][3] = fma2(pd, vb[2].y, o2[r][3]);
            pd = dup2(p4.w);
            o2[r][0] = fma2(pd, va[3].x, o2[r][0]); o2[r][1] = fma2(pd, va[3].y, o2[r][1]);
            o2[r][2] = fma2(pd, vb[3].x, o2[r][2]); o2[r][3] = fma2(pd, vb[3].y, o2[r][3]);
        }
    };
    auto do_exp = [&](int tt) {
        const unsigned wmask = Mb[2 * tt + wc];
        float mv[4];
        #pragma unroll
        for (int c = 0; c < 4; c++)
            mv[c] = ((wmask >> (lcol + 8 * c)) & 1u) ? 0.f : -1e30f;
        #pragma unroll
        for (int r = 0; r < 8; r++) {
            #pragma unroll
            for (int c = 0; c < 4; c++) {
                float2 p = upk(acc[r][c]);
                float e = ex2(p.x + p.y + mv[c]);
                l[r] += e;
                PwS[r * 4 * LDP + 8 * c] = e;
            }
        }
        __syncwarp();            // P is warp-private
    };
    auto zacc = [&]() {
        #pragma unroll
        for (int r = 0; r < 8; r++)
            #pragma unroll
            for (int c = 0; c < 4; c++) acc[r][c] = 0ULL;
    };

    // ---- prologue: Ga{K0->K[0], V0->V[0]}, Gb{K1->K[1]}; QK(0); exp(0) ----
    cp_k(0, 0); cp_v(0, 0); CP_COMMIT();     // Ga
    cp_k(1, 1); CP_COMMIT();                 // Gb
    CP_WAIT(1);                  // Ga landed
    __syncthreads();

    zacc();
    {
        const float* Krow = sm + F_K + jb * LDK;    // K[0] = K(0)
        #pragma unroll 4
        for (int kk = 0; kk < 16; kk++) qk_step(kk, Krow);
    }
    do_exp(0);

    // ---- main loop: ONE barrier per tile; cp issued at top ----
    for (int t = 0; t < NT - 1; t++) {
        CP_WAIT(0);              // all prior groups landed ({K(t+1), V(t)})
        __syncthreads();         // prior-iteration reads of K[t&1], V[(t+1)&1] done

        if (t + 2 < NT) cp_k(t + 2, t & 1);          // K[t&1] is dead
        cp_v(t + 1, (t + 1) & 1);                    // V[(t+1)&1] is dead
        CP_COMMIT();

        const float* Krow = sm + F_K + ((t + 1) & 1) * KSZ + jb * LDK;
        const float* Vs   = sm + F_V + (t & 1) * KSZ;
        zacc();
        #pragma unroll 4
        for (int i = 0; i < 16; i++) {   // fused: QK(t+1) + PV(t)
            qk_step(i, Krow);
            if ((i & 1) == 0) pv_step(i >> 1, Vs);
        }
        do_exp(t + 1);           // warp-drift region: overlaps other warps' fma
    }

    // ---- epilogue: PV(NT-1) ----
    CP_WAIT(0);
    __syncthreads();             // V(NT-1) visible CTA-wide
    {
        const float* Vs = sm + F_V + ((NT - 1) & 1) * KSZ;
        #pragma unroll 4
        for (int i = 0; i < 8; i++) pv_step(i, Vs);
    }

    // ---- row-sum reduction ----
    #pragma unroll
    for (int r = 0; r < 8; r++) {
        float s = l[r];
        s += __shfl_xor_sync(0xffffffffu, s, 1);
        s += __shfl_xor_sync(0xffffffffu, s, 2);
        s += __shfl_xor_sync(0xffffffffu, s, 4);
        l[r] = s;
    }
    if (lcol == 0) {
        #pragma unroll
        for (int r = 0; r < 8; r++) LS[(qrb + 4 * r) * 2 + wc] = l[r];
    }

    // ---- cross-warp O reduce via Ps ----
    __syncthreads();
    if (wc == 1) {
        #pragma unroll
        for (int r = 0; r < 8; r++) {
            int row = qrb + 4 * r;
            float2 a0 = upk(o2[r][0]), a1 = upk(o2[r][1]);
            float2 b0 = upk(o2[r][2]), b1 = upk(o2[r][3]);
            *reinterpret_cast<float4*>(Ps + row * LDP + 4 * lcol)      = make_float4(a0.x, a0.y, a1.x, a1.y);
            *reinterpret_cast<float4*>(Ps + row * LDP + 32 + 4 * lcol) = make_float4(b0.x, b0.y, b1.x, b1.y);
        }
    }
    __syncthreads();

    if (wc == 0) {
        float* Og = outg + ((size_t)bh * SEQ + (size_t)qt * BM) * DIM;
        #pragma unroll
        for (int r = 0; r < 8; r++) {
            int row = qrb + 4 * r;
            float inv = 1.f / (LS[row * 2] + LS[row * 2 + 1]);
            float4 q0 = *reinterpret_cast<const float4*>(Ps + row * LDP + 4 * lcol);
            float4 q1 = *reinterpret_cast<const float4*>(Ps + row * LDP + 32 + 4 * lcol);
            float2 a0 = upk(o2[r][0]), a1 = upk(o2[r][1]);
            float2 b0 = upk(o2[r][2]), b1 = upk(o2[r][3]);
            *reinterpret_cast<float4*>(Og + (size_t)row * DIM + 4 * lcol) =
                make_float4((a0.x + q0.x) * inv, (a0.y + q0.y) * inv,
                            (a1.x + q0.z) * inv, (a1.y + q0.w) * inv);
            *reinterpret_cast<float4*>(Og + (size_t)row * DIM + 32 + 4 * lcol) =
                make_float4((b0.x + q1.x) * inv, (b0.y + q1.y) * inv,
                            (b1.x + q1.z) * inv, (b1.y + q1.w) * inv);
        }
    }
}

extern "C" void kernel_launch(void* const* d_in, const int* in_sizes, int n_in,
                              void* d_out, int out_size)
{
    const float* q = (const float*)d_in[0];
    const float* k = (const float*)d_in[1];
    const float* v = (const float*)d_in[2];
    const unsigned int* mask = (const unsigned int*)d_in[3];
    float* out = (float*)d_out;

    const int smem_bytes = SMEM_FLOATS * (int)sizeof(float);
    cudaFuncSetAttribute(attn_flash10,
                         cudaFuncAttributeMaxDynamicSharedMemorySize, smem_bytes);

    dim3 grid(NT, 64, 1);
    dim3 block(THREADS, 1, 1);
    attn_flash10<<<grid, block, smem_bytes>>>(q, k, v, mask, out);
}

// round 15
// speedup vs baseline: 3.1636x; 1.7981x over previous
#include <cuda_runtime.h>
#include <cstdint>

#define SEQ   2048
#define DIM   64
#define BM    64
#define BN    64
#define NT    (SEQ / BN)
#define SCALE2 0.1803368801111204f   // 0.125 * log2(e)
#define THREADS 128

#define LDK 68            // fp32 staging row stride (floats)
#define KSZ (64 * LDK)
#define PLW 37            // bf16 plane row stride in u32 words (conflict-tuned)
#define PLANE_W (64 * PLW)

// smem float offsets
#define F_KSTG 0                       // 2 x 64 x LDK fp32
#define F_VSTG (2 * KSZ)
#define F_PLANE (F_VSTG + 2 * KSZ)     // 4 planes x PLANE_W u32 (Qs overlaps at start)
#define F_MB   (F_PLANE + 4 * PLANE_W)
#define F_MISC (F_MB + 64)
#define SMEM_FLOATS (F_MISC + 4)

__device__ __forceinline__ void split2(float a, float b, uint32_t& hi, uint32_t& lo) {
    asm("cvt.rn.bf16x2.f32 %0, %1, %2;" : "=r"(hi) : "f"(b), "f"(a));   // a -> low half
    float ah = __uint_as_float(hi << 16);
    float bh = __uint_as_float(hi & 0xffff0000u);
    float ar = a - ah, br = b - bh;
    asm("cvt.rn.bf16x2.f32 %0, %1, %2;" : "=r"(lo) : "f"(br), "f"(ar));
}
__device__ __forceinline__ float ex2(float x) {
    float r; asm("ex2.approx.ftz.f32 %0, %1;" : "=f"(r) : "f"(x)); return r;
}
__device__ __forceinline__ uint32_t smem_u32(const void* p) {
    uint32_t a; asm("{ .reg .u64 t; cvta.to.shared.u64 t, %1; cvt.u32.u64 %0, t; }" : "=r"(a) : "l"(p));
    return a;
}
__device__ __forceinline__ void cp16(uint32_t dst, const void* src) {
    asm volatile("cp.async.cg.shared.global [%0], [%1], 16;" :: "r"(dst), "l"(src));
}
#define CP_COMMIT() asm volatile("cp.async.commit_group;" ::: "memory")
#define CP_WAIT(n)  asm volatile("cp.async.wait_group %0;" :: "n"(n) : "memory")

__device__ __forceinline__ void mma16816(float* c, const uint32_t* a, uint32_t b0, uint32_t b1) {
    asm("mma.sync.aligned.m16n8k16.row.col.f32.bf16.bf16.f32 "
        "{%0,%1,%2,%3}, {%4,%5,%6,%7}, {%8,%9}, {%0,%1,%2,%3};"
        : "+f"(c[0]), "+f"(c[1]), "+f"(c[2]), "+f"(c[3])
        : "r"(a[0]), "r"(a[1]), "r"(a[2]), "r"(a[3]), "r"(b0), "r"(b1));
}

extern "C" __global__ void __launch_bounds__(THREADS, 2)
attn_hmma(const float* __restrict__ qg,
          const float* __restrict__ kg,
          const float* __restrict__ vg,
          const unsigned int* __restrict__ maskg,
          float* __restrict__ outg)
{
    extern __shared__ float sm[];
    uint32_t* KH = (uint32_t*)(sm + F_PLANE);
    uint32_t* KL = KH + PLANE_W;
    uint32_t* VH = KL + PLANE_W;
    uint32_t* VL = VH + PLANE_W;
    float* Qs = sm + F_PLANE;            // overlaps planes; used only before main loop
    unsigned* Mb = (unsigned*)(sm + F_MB);
    int* byteModeP = (int*)(sm + F_MISC);

    const int tid  = threadIdx.x;
    const int wid  = tid >> 5;
    const int lane = tid & 31;
    const int g    = lane >> 2;          // 0..7
    const int tg   = lane & 3;           // 0..3
    const int rw   = wid * 16;           // warp's 16-row band

    const int bh = blockIdx.y;
    const int qt = blockIdx.x;
    const int batch = bh >> 4;

    const float* Qg = qg + ((size_t)bh * SEQ + (size_t)qt * BM) * DIM;
    const float* Kg = kg + (size_t)bh * SEQ * DIM;
    const float* Vg = vg + (size_t)bh * SEQ * DIM;

    // ---- mask dtype detection ----
    if (tid == 0) *byteModeP = 0;
    __syncthreads();
    { unsigned w = maskg[tid]; if (w > 1u && w != 0x3f800000u) atomicOr(byteModeP, 1); }
    __syncthreads();
    const int byteMode = *byteModeP;

    // ---- mask bitmask: 2048 bits ----
    #pragma unroll
    for (int it = 0; it < 16; it++) {
        int i = it * THREADS + tid;
        int e = batch * SEQ + i;
        unsigned keep;
        if (byteMode) keep = (maskg[e >> 2] >> (8 * (e & 3))) & 0xffu;
        else          keep = maskg[e];
        unsigned b = __ballot_sync(0xffffffffu, keep != 0);
        if (lane == 0) Mb[it * 4 + wid] = b;
    }

    const uint32_t sb = smem_u32(sm);
    auto cp_k = [&](int kt, int b) {
        uint32_t base = sb + (F_KSTG + b * KSZ) * 4;
        const float* K0 = Kg + (size_t)kt * BN * DIM;
        #pragma unroll
        for (int it = 0; it < 8; it++) {
            int idx = tid + it * THREADS;
            int row = idx >> 4, c = idx & 15;
            cp16(base + (uint32_t)(row * LDK + 4 * c) * 4, K0 + idx * 4);
        }
    };
    auto cp_v = [&](int kt, int b) {
        uint32_t base = sb + (F_VSTG + b * KSZ) * 4;
        const float* V0 = Vg + (size_t)kt * BN * DIM;
        #pragma unroll
        for (int it = 0; it < 8; it++) {
            int idx = tid + it * THREADS;
            int row = idx >> 4, c = idx & 15;
            cp16(base + (uint32_t)(row * LDK + 4 * c) * 4, V0 + idx * 4);
        }
    };

    // ---- prologue cp: tiles 0 and 1 ----
    cp_k(0, 0); cp_v(0, 0); CP_COMMIT();
    cp_k(1, 1); cp_v(1, 1); CP_COMMIT();

    // ---- Q -> staging (plane region), scale folded ----
    #pragma unroll
    for (int it = 0; it < 8; it++) {
        int idx = tid + it * THREADS;
        int row = idx >> 4, c = idx & 15;
        float4 t = *reinterpret_cast<const float4*>(Qg + row * DIM + c * 4);
        t.x *= SCALE2; t.y *= SCALE2; t.z *= SCALE2; t.w *= SCALE2;
        *reinterpret_cast<float4*>(Qs + row * LDK + 4 * c) = t;
    }
    __syncthreads();

    // ---- build Q fragments in registers (once) ----
    uint32_t QH[4][4], QL[4][4];
    #pragma unroll
    for (int k4 = 0; k4 < 4; k4++) {
        float2 qa = *reinterpret_cast<const float2*>(Qs + (rw + g) * LDK + 16 * k4 + 2 * tg);
        float2 qb = *reinterpret_cast<const float2*>(Qs + (rw + g + 8) * LDK + 16 * k4 + 2 * tg);
        float2 qc = *reinterpret_cast<const float2*>(Qs + (rw + g) * LDK + 16 * k4 + 8 + 2 * tg);
        float2 qd = *reinterpret_cast<const float2*>(Qs + (rw + g + 8) * LDK + 16 * k4 + 8 + 2 * tg);
        split2(qa.x, qa.y, QH[k4][0], QL[k4][0]);
        split2(qb.x, qb.y, QH[k4][1], QL[k4][1]);
        split2(qc.x, qc.y, QH[k4][2], QL[k4][2]);
        split2(qd.x, qd.y, QH[k4][3], QL[k4][3]);
    }

    float O[8][4];
    #pragma unroll
    for (int n = 0; n < 8; n++)
        #pragma unroll
        for (int e = 0; e < 4; e++) O[n][e] = 0.f;
    float lg = 0.f, lg8 = 0.f;

    for (int t = 0; t < NT; t++) {
        if (t + 1 < NT) { CP_WAIT(1); } else { CP_WAIT(0); }
        __syncthreads();              // staging[t] landed; prior plane reads done

        // ---- convert K(t) -> KH/KL planes ----
        {
            int j = tid & 63, ch = tid >> 6;
            const float* Kst = sm + F_KSTG + (t & 1) * KSZ + j * LDK + 32 * ch;
            uint32_t wbase = j * PLW + 16 * ch;
            #pragma unroll
            for (int w8 = 0; w8 < 8; w8++) {
                float4 v = *reinterpret_cast<const float4*>(Kst + 4 * w8);
                uint32_t h0, l0, h1, l1;
                split2(v.x, v.y, h0, l0);
                split2(v.z, v.w, h1, l1);
                KH[wbase + 2 * w8] = h0; KH[wbase + 2 * w8 + 1] = h1;
                KL[wbase + 2 * w8] = l0; KL[wbase + 2 * w8 + 1] = l1;
            }
        }
        // ---- convert V(t) -> transposed VH/VL planes ----
        {
            int jp = lane, dq = wid;
            const float* V0 = sm + F_VSTG + (t & 1) * KSZ + (2 * jp) * LDK + 16 * dq;
            const float* V1 = V0 + LDK;
            #pragma unroll
            for (int c4 = 0; c4 < 4; c4++) {
                float4 x = *reinterpret_cast<const float4*>(V0 + 4 * c4);
                float4 y = *reinterpret_cast<const float4*>(V1 + 4 * c4);
                int d = 16 * dq + 4 * c4;
                uint32_t h, l;
                split2(x.x, y.x, h, l); VH[(d + 0) * PLW + jp] = h; VL[(d + 0) * PLW + jp] = l;
                split2(x.y, y.y, h, l); VH[(d + 1) * PLW + jp] = h; VL[(d + 1) * PLW + jp] = l;
                split2(x.z, y.z, h, l); VH[(d + 2) * PLW + jp] = h; VL[(d + 2) * PLW + jp] = l;
                split2(x.w, y.w, h, l); VH[(d + 3) * PLW + jp] = h; VL[(d + 3) * PLW + jp] = l;
            }
        }
        __syncthreads();              // planes ready; staging[t] consumed

        if (t + 2 < NT) { cp_k(t + 2, t & 1); cp_v(t + 2, t & 1); CP_COMMIT(); }

        // ---- QK: S[16x64] via bf16-split HMMA ----
        float S[8][4];
        #pragma unroll
        for (int n = 0; n < 8; n++) {
            S[n][0] = 0.f; S[n][1] = 0.f; S[n][2] = 0.f; S[n][3] = 0.f;
            uint32_t rbase = (8 * n + g) * PLW;
            #pragma unroll
            for (int k4 = 0; k4 < 4; k4++) {
                uint32_t w = rbase + 8 * k4 + tg;
                uint32_t bh0 = KH[w], bh1 = KH[w + 4];
                uint32_t bl0 = KL[w], bl1 = KL[w + 4];
                mma16816(S[n], QH[k4], bh0, bh1);
                mma16816(S[n], QH[k4], bl0, bl1);
                mma16816(S[n], QL[k4], bh0, bh1);
            }
        }

        // ---- exp in registers; build P fragments (D-frag == A-frag layout) ----
        uint32_t PH[4][4], PL[4][4];
        #pragma unroll
        for (int n = 0; n < 8; n++) {
            unsigned wm = Mb[2 * t + (n >> 2)];
            int c0 = 8 * (n & 3) + 2 * tg;
            float m0 = ((wm >> c0) & 1u)       ? 0.f : -1e30f;
            float m1 = ((wm >> (c0 + 1)) & 1u) ? 0.f : -1e30f;
            float p0 = ex2(S[n][0] + m0);
            float p1 = ex2(S[n][1] + m1);
            float p2 = ex2(S[n][2] + m0);
            float p3 = ex2(S[n][3] + m1);
            lg += p0 + p1; lg8 += p2 + p3;
            int kp = n >> 1, h = (n & 1) * 2;
            split2(p0, p1, PH[kp][h],     PL[kp][h]);
            split2(p2, p3, PH[kp][h + 1], PL[kp][h + 1]);
        }

        // ---- PV: O += P V via bf16-split HMMA (V from transposed planes) ----
        #pragma unroll
        for (int n = 0; n < 8; n++) {
            uint32_t rbase = (8 * n + g) * PLW;
            #pragma unroll
            for (int k4 = 0; k4 < 4; k4++) {
                uint32_t w = rbase + 8 * k4 + tg;
                uint32_t vh0 = VH[w], vh1 = VH[w + 4];
                uint32_t vl0 = VL[w], vl1 = VL[w + 4];
                mma16816(O[n], PH[k4], vh0, vh1);
                mma16816(O[n], PH[k4], vl0, vl1);
                mma16816(O[n], PL[k4], vh0, vh1);
            }
        }
    }

    // ---- l reduction over the 4 tg lanes (rows fully warp-owned) ----
    lg  += __shfl_xor_sync(0xffffffffu, lg, 1);
    lg  += __shfl_xor_sync(0xffffffffu, lg, 2);
    lg8 += __shfl_xor_sync(0xffffffffu, lg8, 1);
    lg8 += __shfl_xor_sync(0xffffffffu, lg8, 2);
    const float inv0 = 1.f / lg, inv8 = 1.f / lg8;

    // ---- store O ----
    float* Og = outg + ((size_t)bh * SEQ + (size_t)qt * BM) * DIM;
    const int row0 = rw + g, row1 = rw + g + 8;
    #pragma unroll
    for (int n = 0; n < 8; n++) {
        int col = 8 * n + 2 * tg;
        *reinterpret_cast<float2*>(Og + (size_t)row0 * DIM + col) =
            make_float2(O[n][0] * inv0, O[n][1] * inv0);
        *reinterpret_cast<float2*>(Og + (size_t)row1 * DIM + col) =
            make_float2(O[n][2] * inv8, O[n][3] * inv8);
    }
}

extern "C" void kernel_launch(void* const* d_in, const int* in_sizes, int n_in,
                              void* d_out, int out_size)
{
    const float* q = (const float*)d_in[0];
    const float* k = (const float*)d_in[1];
    const float* v = (const float*)d_in[2];
    const unsigned int* mask = (const unsigned int*)d_in[3];
    float* out = (float*)d_out;

    const int smem_bytes = SMEM_FLOATS * (int)sizeof(float);   // ~105.3 KB
    cudaFuncSetAttribute(attn_hmma,
                         cudaFuncAttributeMaxDynamicSharedMemorySize, smem_bytes);

    dim3 grid(NT, 64, 1);
    dim3 block(THREADS, 1, 1);
    attn_hmma<<<grid, block, smem_bytes>>>(q, k, v, mask, out);
}

// round 17
// speedup vs baseline: 4.0670x; 1.2856x over previous
#include <cuda_runtime.h>
#include <cstdint>

#define SEQ   2048
#define DIM   64
#define BM    64
#define BN    64
#define NT    (SEQ / BN)
#define SCALE2 0.1803368801111204f   // 0.125 * log2(e)
#define THREADS 128

#define PLW   36                  // plane row stride in u32 words (16B-aligned, conflict-free)
#define PLSZ  (64 * PLW)          // words per plane tile in smem

typedef unsigned long long ull;

// pre-converted bf16 planes: K rows j x 32 words (k-pairs); V transposed: rows d x 32 words (j-pairs)
__device__ uint32_t KHg[(size_t)64 * 2048 * 32];
__device__ uint32_t KLg[(size_t)64 * 2048 * 32];
__device__ uint32_t VHg[(size_t)64 * 2048 * 32];
__device__ uint32_t VLg[(size_t)64 * 2048 * 32];

__device__ __forceinline__ void split2(float a, float b, uint32_t& hi, uint32_t& lo) {
    asm("cvt.rn.bf16x2.f32 %0, %1, %2;" : "=r"(hi) : "f"(b), "f"(a));   // a -> low half
    float ah = __uint_as_float(hi << 16);
    float bh = __uint_as_float(hi & 0xffff0000u);
    float ar = a - ah, br = b - bh;
    asm("cvt.rn.bf16x2.f32 %0, %1, %2;" : "=r"(lo) : "f"(br), "f"(ar));
}
__device__ __forceinline__ float ex2(float x) {
    float r; asm("ex2.approx.ftz.f32 %0, %1;" : "=f"(r) : "f"(x)); return r;
}
__device__ __forceinline__ uint32_t smem_u32(const void* p) {
    uint32_t a; asm("{ .reg .u64 t; cvta.to.shared.u64 t, %1; cvt.u32.u64 %0, t; }" : "=r"(a) : "l"(p));
    return a;
}
__device__ __forceinline__ void cp16(uint32_t dst, const void* src) {
    asm volatile("cp.async.cg.shared.global [%0], [%1], 16;" :: "r"(dst), "l"(src));
}
#define CP_COMMIT() asm volatile("cp.async.commit_group;" ::: "memory")
#define CP_WAIT(n)  asm volatile("cp.async.wait_group %0;" :: "n"(n) : "memory")

__device__ __forceinline__ void mma16816(float* c, const uint32_t* a, uint32_t b0, uint32_t b1) {
    asm("mma.sync.aligned.m16n8k16.row.col.f32.bf16.bf16.f32 "
        "{%0,%1,%2,%3}, {%4,%5,%6,%7}, {%8,%9}, {%0,%1,%2,%3};"
        : "+f"(c[0]), "+f"(c[1]), "+f"(c[2]), "+f"(c[3])
        : "r"(a[0]), "r"(a[1]), "r"(a[2]), "r"(a[3]), "r"(b0), "r"(b1));
}

// ---------------- pre-conversion kernel: K/V fp32 -> bf16 hi/lo plane images ----------------
extern "C" __global__ void __launch_bounds__(THREADS)
convert_kv(const float* __restrict__ kg, const float* __restrict__ vg)
{
    __shared__ float vs[64 * 68];
    __shared__ uint32_t vw[2][64 * 32];

    const int t  = blockIdx.x;      // key tile 0..31
    const int bh = blockIdx.y;      // 0..63
    const int tid = threadIdx.x;

    const float* K0 = kg + ((size_t)bh * SEQ + (size_t)t * BN) * DIM;
    const float* V0 = vg + ((size_t)bh * SEQ + (size_t)t * BN) * DIM;

    // ---- K: direct convert, word w = k/2, rows j ----
    #pragma unroll
    for (int it = 0; it < 8; it++) {
        int idx = it * THREADS + tid;          // 1024 float4
        int j = idx >> 4, c4 = idx & 15;
        float4 v = *reinterpret_cast<const float4*>(K0 + j * DIM + 4 * c4);
        uint32_t h0, l0, h1, l1;
        split2(v.x, v.y, h0, l0);
        split2(v.z, v.w, h1, l1);
        size_t o = ((size_t)bh * SEQ + (size_t)t * BN + j) * 32 + 2 * c4;
        *reinterpret_cast<ull*>(&KHg[o]) = (ull)h0 | ((ull)h1 << 32);
        *reinterpret_cast<ull*>(&KLg[o]) = (ull)l0 | ((ull)l1 << 32);
    }

    // ---- V: stage fp32, transpose-split to word buffers, linear store ----
    #pragma unroll
    for (int it = 0; it < 8; it++) {
        int idx = it * THREADS + tid;
        int j = idx >> 4, c4 = idx & 15;
        *reinterpret_cast<float4*>(&vs[j * 68 + 4 * c4]) =
            *reinterpret_cast<const float4*>(V0 + j * DIM + 4 * c4);
    }
    __syncthreads();
    {
        int d = tid >> 1, half = tid & 1;
        #pragma unroll
        for (int i = 0; i < 16; i++) {
            int w = 16 * half + i;             // j-pair index
            uint32_t h, l;
            split2(vs[(2 * w) * 68 + d], vs[(2 * w + 1) * 68 + d], h, l);
            vw[0][d * 32 + w] = h;
            vw[1][d * 32 + w] = l;
        }
    }
    __syncthreads();
    {
        size_t vb = ((size_t)bh * 32 + t) * 2048;
        #pragma unroll
        for (int it = 0; it < 4; it++) {
            int ci = it * THREADS + tid;       // 512 16B chunks
            *reinterpret_cast<uint4*>(&VHg[vb + 4 * ci]) = *reinterpret_cast<uint4*>(&vw[0][4 * ci]);
            *reinterpret_cast<uint4*>(&VLg[vb + 4 * ci]) = *reinterpret_cast<uint4*>(&vw[1][4 * ci]);
        }
    }
}

// ---------------- main attention kernel ----------------
extern "C" __global__ void __launch_bounds__(THREADS, 3)
attn_hmma2(const float* __restrict__ qg,
           const unsigned int* __restrict__ maskg,
           float* __restrict__ outg)
{
    extern __shared__ uint32_t smw[];
    // layout: [buf 2][plane 4][PLSZ] ; Mb[64] ; byteMode
    uint32_t* Mb = smw + 8 * PLSZ;
    int* byteModeP = (int*)(smw + 8 * PLSZ + 64);

    const int tid  = threadIdx.x;
    const int wid  = tid >> 5;
    const int lane = tid & 31;
    const int g    = lane >> 2;
    const int tg   = lane & 3;
    const int rw   = wid * 16;

    const int bh = blockIdx.y;
    const int qt = blockIdx.x;
    const int batch = bh >> 4;

    // ---- mask dtype detection ----
    if (tid == 0) *byteModeP = 0;
    __syncthreads();
    { unsigned w = maskg[tid]; if (w > 1u && w != 0x3f800000u) atomicOr(byteModeP, 1); }
    __syncthreads();
    const int byteMode = *byteModeP;

    // ---- cp prologue: plane tiles 0 and 1 ----
    const uint32_t sb = smem_u32(smw);
    auto cp_tile = [&](int kt, int b) {
        size_t kb = ((size_t)bh * SEQ + (size_t)kt * BN) * 32;
        size_t vb = ((size_t)bh * 32 + kt) * 2048;
        uint32_t dst = sb + (uint32_t)(b * 4 * PLSZ) * 4;
        #pragma unroll
        for (int it = 0; it < 4; it++) {
            int idx = it * THREADS + tid;      // 512 chunks
            int row = idx >> 3, c = idx & 7;
            uint32_t doff = (uint32_t)(row * PLW + 4 * c) * 4;
            cp16(dst + doff,                KHg + kb + 4 * idx);
            cp16(dst + PLSZ * 4 + doff,     KLg + kb + 4 * idx);
            cp16(dst + 2 * PLSZ * 4 + doff, VHg + vb + 4 * idx);
            cp16(dst + 3 * PLSZ * 4 + doff, VLg + vb + 4 * idx);
        }
    };
    cp_tile(0, 0); CP_COMMIT();
    cp_tile(1, 1); CP_COMMIT();

    // ---- mask bitmask ----
    #pragma unroll
    for (int it = 0; it < 16; it++) {
        int i = it * THREADS + tid;
        int e = batch * SEQ + i;
        unsigned keep;
        if (byteMode) keep = (maskg[e >> 2] >> (8 * (e & 3))) & 0xffu;
        else          keep = maskg[e];
        unsigned b = __ballot_sync(0xffffffffu, keep != 0);
        if (lane == 0) Mb[it * 4 + wid] = b;
    }

    // ---- Q fragments via direct LDG (once) ----
    uint32_t QH[4][4], QL[4][4];
    {
        const float* Qb = qg + ((size_t)bh * SEQ + (size_t)qt * BM) * DIM;
        #pragma unroll
        for (int k4 = 0; k4 < 4; k4++) {
            const float* q0 = Qb + (rw + g) * DIM + 16 * k4 + 2 * tg;
            const float* q1 = q0 + 8 * DIM;
            float2 qa = *reinterpret_cast<const float2*>(q0);
            float2 qb = *reinterpret_cast<const float2*>(q1);
            float2 qc = *reinterpret_cast<const float2*>(q0 + 8);
            float2 qd = *reinterpret_cast<const float2*>(q1 + 8);
            split2(qa.x * SCALE2, qa.y * SCALE2, QH[k4][0], QL[k4][0]);
            split2(qb.x * SCALE2, qb.y * SCALE2, QH[k4][1], QL[k4][1]);
            split2(qc.x * SCALE2, qc.y * SCALE2, QH[k4][2], QL[k4][2]);
            split2(qd.x * SCALE2, qd.y * SCALE2, QH[k4][3], QL[k4][3]);
        }
    }

    float O[8][4];
    #pragma unroll
    for (int n = 0; n < 8; n++)
        #pragma unroll
        for (int e = 0; e < 4; e++) O[n][e] = 0.f;
    float lg = 0.f, lg8 = 0.f;

    for (int t = 0; t < NT; t++) {
        if (t + 1 < NT) { CP_WAIT(1); } else { CP_WAIT(0); }
        __syncthreads();                  // plane tile t visible CTA-wide

        const uint32_t* KH = smw + (t & 1) * 4 * PLSZ;
        const uint32_t* KL = KH + PLSZ;
        const uint32_t* VH = KH + 2 * PLSZ;
        const uint32_t* VL = KH + 3 * PLSZ;

        // ---- QK: S[16x64] bf16-split HMMA ----
        float S[8][4];
        #pragma unroll
        for (int n = 0; n < 8; n++) {
            S[n][0] = 0.f; S[n][1] = 0.f; S[n][2] = 0.f; S[n][3] = 0.f;
            uint32_t rbase = (8 * n + g) * PLW;
            #pragma unroll
            for (int k4 = 0; k4 < 4; k4++) {
                uint32_t w = rbase + 8 * k4 + tg;
                uint32_t bh0 = KH[w], bh1 = KH[w + 4];
                uint32_t bl0 = KL[w], bl1 = KL[w + 4];
                mma16816(S[n], QH[k4], bh0, bh1);
                mma16816(S[n], QH[k4], bl0, bl1);
                mma16816(S[n], QL[k4], bh0, bh1);
            }
        }

        // ---- exp in registers; P fragments (D-frag == A-frag layout) ----
        uint32_t PH[4][4], PL[4][4];
        #pragma unroll
        for (int n = 0; n < 8; n++) {
            unsigned wm = Mb[2 * t + (n >> 2)];
            int c0 = 8 * (n & 3) + 2 * tg;
            float m0 = ((wm >> c0) & 1u)       ? 0.f : -1e30f;
            float m1 = ((wm >> (c0 + 1)) & 1u) ? 0.f : -1e30f;
            float p0 = ex2(S[n][0] + m0);
            float p1 = ex2(S[n][1] + m1);
            float p2 = ex2(S[n][2] + m0);
            float p3 = ex2(S[n][3] + m1);
            lg += p0 + p1; lg8 += p2 + p3;
            int kp = n >> 1, h = (n & 1) * 2;
            split2(p0, p1, PH[kp][h],     PL[kp][h]);
            split2(p2, p3, PH[kp][h + 1], PL[kp][h + 1]);
        }

        // ---- PV: O += P V ----
        #pragma unroll
        for (int n = 0; n < 8; n++) {
            uint32_t rbase = (8 * n + g) * PLW;
            #pragma unroll
            for (int k4 = 0; k4 < 4; k4++) {
                uint32_t w = rbase + 8 * k4 + tg;
                uint32_t vh0 = VH[w], vh1 = VH[w + 4];
                uint32_t vl0 = VL[w], vl1 = VL[w + 4];
                mma16816(O[n], PH[k4], vh0, vh1);
                mma16816(O[n], PH[k4], vl0, vl1);
                mma16816(O[n], PL[k4], vh0, vh1);
            }
        }

        __syncthreads();                  // all reads of tile t done
        if (t + 2 < NT) { cp_tile(t + 2, t & 1); CP_COMMIT(); }
    }

    // ---- l reduction over 4 tg lanes ----
    lg  += __shfl_xor_sync(0xffffffffu, lg, 1);
    lg  += __shfl_xor_sync(0xffffffffu, lg, 2);
    lg8 += __shfl_xor_sync(0xffffffffu, lg8, 1);
    lg8 += __shfl_xor_sync(0xffffffffu, lg8, 2);
    const float inv0 = 1.f / lg, inv8 = 1.f / lg8;

    // ---- store ----
    float* Og = outg + ((size_t)bh * SEQ + (size_t)qt * BM) * DIM;
    const int row0 = rw + g, row1 = rw + g + 8;
    #pragma unroll
    for (int n = 0; n < 8; n++) {
        int col = 8 * n + 2 * tg;
        *reinterpret_cast<float2*>(Og + (size_t)row0 * DIM + col) =
            make_float2(O[n][0] * inv0, O[n][1] * inv0);
        *reinterpret_cast<float2*>(Og + (size_t)row1 * DIM + col) =
            make_float2(O[n][2] * inv8, O[n][3] * inv8);
    }
}

extern "C" void kernel_launch(void* const* d_in, const int* in_sizes, int n_in,
                              void* d_out, int out_size)
{
    const float* q = (const float*)d_in[0];
    const float* k = (const float*)d_in[1];
    const float* v = (const float*)d_in[2];
    const unsigned int* mask = (const unsigned int*)d_in[3];
    float* out = (float*)d_out;

    // pre-convert K/V to bf16 plane images
    dim3 cgrid(NT, 64, 1);
    convert_kv<<<cgrid, THREADS>>>(k, v);

    const int smem_bytes = (8 * PLSZ + 80) * (int)sizeof(uint32_t);  // ~74 KB
    cudaFuncSetAttribute(attn_hmma2,
                         cudaFuncAttributeMaxDynamicSharedMemorySize, smem_bytes);

    dim3 grid(NT, 64, 1);
    attn_hmma2<<<grid, THREADS, smem_bytes>>>(q, mask, out);
}